// round 5
// baseline (speedup 1.0000x reference)
#include <cuda_runtime.h>
#include <cuda.h>
#include <math.h>
#include <cstdint>

// ---------------- problem constants ----------------
#define NTOK   4096          // B*S
#define HDIM   4096
#define NEXP   8
#define TOPK   2
#define CAP    1536
#define NSEL   (NTOK*TOPK)

#define DISPATCH_ELEMS  ((long long)NTOK*NEXP*CAP)
#define PROBS_OFF       (2LL*DISPATCH_ELEMS)
#define AUX_OFF         (PROBS_OFF + (long long)NTOK*NEXP)

// ---------------- device scratch ----------------
__device__ float g_h[(size_t)NTOK * HDIM];
__device__ float g_logits[NTOK * NEXP];
__device__ int   g_flat_idx[NSEL];
__device__ float g_flat_prob[NSEL];
__device__ int   g_pos[NSEL];
__device__ int   g_counts[NEXP];

// ---------------- helpers ----------------
__device__ __forceinline__ void cpasync16(uint32_t dst, const void* src) {
    asm volatile("cp.async.cg.shared.global [%0], [%1], 16;\n" :: "r"(dst), "l"(src));
}
#define CP_COMMIT() asm volatile("cp.async.commit_group;\n" ::: "memory")
#define CP_WAIT(n)  asm volatile("cp.async.wait_group %0;\n" :: "n"(n) : "memory")

__device__ __forceinline__ uint32_t smem_u32(const void* p) {
    uint32_t a;
    asm("{ .reg .u64 t; cvta.to.shared.u64 t, %1; cvt.u32.u64 %0, t; }" : "=r"(a) : "l"(p));
    return a;
}

__device__ __forceinline__ float tf32_hi(float v) {
    return __uint_as_float(__float_as_uint(v) & 0xFFFFE000u);
}

// mma.sync m16n8k8 tf32: D += A x B, fp32 accum. Base ISA (sm_80+).
__device__ __forceinline__ void mma_tf32(float c[4],
                                         uint32_t a0, uint32_t a1, uint32_t a2, uint32_t a3,
                                         uint32_t b0, uint32_t b1) {
    asm volatile(
        "mma.sync.aligned.m16n8k8.row.col.f32.tf32.tf32.f32 "
        "{%0,%1,%2,%3}, {%4,%5,%6,%7}, {%8,%9}, {%0,%1,%2,%3};"
        : "+f"(c[0]), "+f"(c[1]), "+f"(c[2]), "+f"(c[3])
        : "r"(a0), "r"(a1), "r"(a2), "r"(a3), "r"(b0), "r"(b1));
}

// ---------------- GEMM1 + fused output zeroing ----------------
// A[M,K] row-major, W1[K,N] row-major (col-major B for .row.col mma).
// 512 threads, 16 warps, warp tile 64x16 -> ~100 regs/thread, 16 warps/SM.
// Blocks with bid%5==4 zero the dispatch/combine output instead (overlaps
// DRAM-store work with tensor-pipe work).
#define BM 128
#define BN 128
#define BK 32
#define ASTRIDE 36     // pad 4 -> conflict-free A frag
#define BSTRIDE 136    // pad 8 -> conflict-free B frag
#define ABYTES (BM * ASTRIDE * 4)     // 18432
#define BBYTES (BK * BSTRIDE * 4)     // 17408
#define STAGEBYTES (ABYTES + BBYTES)  // 35840
#define GSMEM (2 * STAGEBYTES)        // 71680
#define GRID_TILE 1024                // (4096/128)^2
#define GRID_ZERO 256
#define GRID_TOTAL (GRID_TILE + GRID_TILE / 4)   // 1280

__global__ __launch_bounds__(512) void gemm1_tc(
    const float* __restrict__ A, const float* __restrict__ B,
    const float* __restrict__ bias, float* __restrict__ C,
    float4* __restrict__ zout, long long zn4)
{
    const int bid = blockIdx.x;
    const int tid = threadIdx.x;

    // ---- zero blocks: interleaved, stream 402MB of output zeroing ----
    if ((bid % 5) == 4) {
        const int zid = bid / 5;                       // 0..255
        long long i = (long long)zid * 512 + tid;
        const long long stride = (long long)GRID_ZERO * 512;
        float4 z = make_float4(0.f, 0.f, 0.f, 0.f);
        for (; i < zn4; i += stride) zout[i] = z;
        if (zid == 0 && tid < NEXP) g_counts[tid] = 0;
        return;
    }
    const int tile = (bid / 5) * 4 + (bid % 5);        // 0..1023

    extern __shared__ float smem[];
    const int warp = tid >> 5, lane = tid & 31;
    const int wm = (warp & 1) * 64;        // warp m-offset
    const int wn = (warp >> 1) * 16;       // warp n-offset (8 groups of 16)
    const int row0 = (tile >> 5) * BM;
    const int col0 = (tile & 31) * BN;
    const int r = lane >> 2, cq = lane & 3;

    const uint32_t sb = smem_u32(smem);

    float acc[4][2][4];
    #pragma unroll
    for (int i = 0; i < 4; i++)
        #pragma unroll
        for (int j = 0; j < 2; j++)
            #pragma unroll
            for (int f = 0; f < 4; f++) acc[i][j][f] = 0.f;

    auto fill = [&](int buf, int kc) {
        const uint32_t st = sb + buf * STAGEBYTES;
        #pragma unroll
        for (int t = 0; t < 2; t++) {          // A: 1024 x 16B chunks
            int o = tid + t * 512;
            int rr = o >> 3, c16 = o & 7;
            cpasync16(st + (rr * ASTRIDE + c16 * 4) * 4,
                      A + (size_t)(row0 + rr) * HDIM + kc + c16 * 4);
        }
        #pragma unroll
        for (int t = 0; t < 2; t++) {          // B: 1024 x 16B chunks
            int o = tid + t * 512;
            int rr = o >> 5, c16 = o & 31;
            cpasync16(st + ABYTES + (rr * BSTRIDE + c16 * 4) * 4,
                      B + (size_t)(kc + rr) * HDIM + col0 + c16 * 4);
        }
    };

    fill(0, 0);
    CP_COMMIT();

    const int NCHUNK = HDIM / BK;   // 128
    for (int c = 0; c < NCHUNK; ++c) {
        if (c + 1 < NCHUNK) { fill((c + 1) & 1, (c + 1) * BK); CP_COMMIT(); CP_WAIT(1); }
        else                { CP_WAIT(0); }
        __syncthreads();

        const float* As = smem + ((c & 1) * STAGEBYTES) / 4;
        const float* Bs = As + ABYTES / 4;

        #pragma unroll
        for (int kk = 0; kk < BK; kk += 8) {
            // A frags (m16n8k8 tf32): a0=(r,cq) a1=(r+8,cq) a2=(r,cq+4) a3=(r+8,cq+4)
            uint32_t ahi[4][4], alo[4][4];
            #pragma unroll
            for (int mt = 0; mt < 4; mt++) {
                const float* pa = As + (size_t)(wm + mt * 16 + r) * ASTRIDE + kk + cq;
                float a0 = pa[0];
                float a1 = pa[8 * ASTRIDE];
                float a2 = pa[4];
                float a3 = pa[8 * ASTRIDE + 4];
                float h0 = tf32_hi(a0), h1 = tf32_hi(a1), h2 = tf32_hi(a2), h3 = tf32_hi(a3);
                ahi[mt][0] = __float_as_uint(h0); alo[mt][0] = __float_as_uint(a0 - h0);
                ahi[mt][1] = __float_as_uint(h1); alo[mt][1] = __float_as_uint(a1 - h1);
                ahi[mt][2] = __float_as_uint(h2); alo[mt][2] = __float_as_uint(a2 - h2);
                ahi[mt][3] = __float_as_uint(h3); alo[mt][3] = __float_as_uint(a3 - h3);
            }
            // B frags: b0=(k=cq, n=r), b1=(k=cq+4, n=r)
            #pragma unroll
            for (int nt = 0; nt < 2; nt++) {
                const float* pb = Bs + (size_t)(kk + cq) * BSTRIDE + wn + nt * 8 + r;
                float b0 = pb[0], b1 = pb[4 * BSTRIDE];
                float h0 = tf32_hi(b0), h1 = tf32_hi(b1);
                uint32_t bh0 = __float_as_uint(h0), bl0 = __float_as_uint(b0 - h0);
                uint32_t bh1 = __float_as_uint(h1), bl1 = __float_as_uint(b1 - h1);
                #pragma unroll
                for (int mt = 0; mt < 4; mt++) {
                    mma_tf32(acc[mt][nt], ahi[mt][0], ahi[mt][1], ahi[mt][2], ahi[mt][3],
                             bh0, bh1);
                    mma_tf32(acc[mt][nt], ahi[mt][0], ahi[mt][1], ahi[mt][2], ahi[mt][3],
                             bl0, bl1);
                    mma_tf32(acc[mt][nt], alo[mt][0], alo[mt][1], alo[mt][2], alo[mt][3],
                             bh0, bh1);
                }
            }
        }
        __syncthreads();
    }

    // ---- epilogue: relu(acc + bias) -> C ----
    #pragma unroll
    for (int mt = 0; mt < 4; mt++) {
        #pragma unroll
        for (int nt = 0; nt < 2; nt++) {
            int col = col0 + wn + nt * 8 + 2 * cq;
            float bx = __ldg(bias + col), by = __ldg(bias + col + 1);
            int rowa = row0 + wm + mt * 16 + r;
            float2 v0, v1;
            v0.x = fmaxf(acc[mt][nt][0] + bx, 0.f);
            v0.y = fmaxf(acc[mt][nt][1] + by, 0.f);
            v1.x = fmaxf(acc[mt][nt][2] + bx, 0.f);
            v1.y = fmaxf(acc[mt][nt][3] + by, 0.f);
            *(float2*)(C + (size_t)rowa * HDIM + col) = v0;
            *(float2*)(C + (size_t)(rowa + 8) * HDIM + col) = v1;
        }
    }
}

// ---------------- GEMM2: logits = h @ W2 + b2 (one warp per token) ----------------
__global__ void gemm2_kernel(const float* __restrict__ h, const float* __restrict__ W2,
                             const float* __restrict__ b2, float* __restrict__ logits)
{
    int warp = (blockIdx.x * blockDim.x + threadIdx.x) >> 5;
    int lane = threadIdx.x & 31;
    if (warp >= NTOK) return;
    const float* hr = h + (size_t)warp * HDIM;

    float acc[NEXP];
    #pragma unroll
    for (int e = 0; e < NEXP; e++) acc[e] = 0.f;

    for (int k0 = lane * 4; k0 < HDIM; k0 += 128) {
        float4 hv = *(const float4*)(hr + k0);
        float hvv[4] = {hv.x, hv.y, hv.z, hv.w};
        #pragma unroll
        for (int j = 0; j < 4; j++) {
            const float* w = W2 + (size_t)(k0 + j) * NEXP;
            float4 w0 = *(const float4*)w;
            float4 w1 = *(const float4*)(w + 4);
            acc[0] += hvv[j] * w0.x; acc[1] += hvv[j] * w0.y;
            acc[2] += hvv[j] * w0.z; acc[3] += hvv[j] * w0.w;
            acc[4] += hvv[j] * w1.x; acc[5] += hvv[j] * w1.y;
            acc[6] += hvv[j] * w1.z; acc[7] += hvv[j] * w1.w;
        }
    }
    #pragma unroll
    for (int e = 0; e < NEXP; e++) {
        #pragma unroll
        for (int off = 16; off > 0; off >>= 1)
            acc[e] += __shfl_down_sync(0xffffffffu, acc[e], off);
    }
    if (lane == 0) {
        #pragma unroll
        for (int e = 0; e < NEXP; e++)
            logits[warp * NEXP + e] = acc[e] + b2[e];
    }
}

// ---------------- softmax + top-2 ----------------
__global__ void topk_kernel(const float* __restrict__ logits, float* __restrict__ probs_out)
{
    int t = blockIdx.x * blockDim.x + threadIdx.x;
    if (t >= NTOK) return;
    float l[NEXP];
    float m = -1e30f;
    #pragma unroll
    for (int e = 0; e < NEXP; e++) { l[e] = logits[t * NEXP + e]; m = fmaxf(m, l[e]); }
    float s = 0.f;
    #pragma unroll
    for (int e = 0; e < NEXP; e++) { l[e] = expf(l[e] - m); s += l[e]; }
    float inv = 1.f / s;
    float p[NEXP];
    #pragma unroll
    for (int e = 0; e < NEXP; e++) { p[e] = l[e] * inv; probs_out[t * NEXP + e] = p[e]; }

    int i1 = 0; float p1 = p[0];
    #pragma unroll
    for (int e = 1; e < NEXP; e++) if (p[e] > p1) { p1 = p[e]; i1 = e; }
    int i2 = -1; float p2 = -1.f;
    #pragma unroll
    for (int e = 0; e < NEXP; e++) if (e != i1 && p[e] > p2) { p2 = p[e]; i2 = e; }

    float norm = 1.f / (p1 + p2 + 1e-8f);
    g_flat_idx[2 * t + 0] = i1;
    g_flat_idx[2 * t + 1] = i2;
    g_flat_prob[2 * t + 0] = p1 * norm;
    g_flat_prob[2 * t + 1] = p2 * norm;
    atomicAdd(&g_counts[i1], 1);
    atomicAdd(&g_counts[i2], 1);
}

// ---------------- exclusive per-expert position scan ----------------
__device__ __forceinline__ uint4 add4(uint4 a, uint4 b) {
    return make_uint4(a.x + b.x, a.y + b.y, a.z + b.z, a.w + b.w);
}
__device__ __forceinline__ uint4 sub4(uint4 a, uint4 b) {
    return make_uint4(a.x - b.x, a.y - b.y, a.z - b.z, a.w - b.w);
}
__global__ __launch_bounds__(1024) void scan_kernel()
{
    const int tid = threadIdx.x;
    const int lane = tid & 31, wid = tid >> 5;

    int e[8];
    uint4 pre[8];
    uint4 run = make_uint4(0, 0, 0, 0);
    #pragma unroll
    for (int i = 0; i < 8; i++) {
        e[i] = g_flat_idx[tid * 8 + i];
        pre[i] = run;
        unsigned word = (unsigned)e[i] >> 1;
        unsigned add = 1u << ((e[i] & 1) * 16);
        if (word == 0) run.x += add;
        else if (word == 1) run.y += add;
        else if (word == 2) run.z += add;
        else run.w += add;
    }
    const uint4 own = run;

    uint4 incl = own;
    #pragma unroll
    for (int off = 1; off < 32; off <<= 1) {
        unsigned vx = __shfl_up_sync(0xffffffffu, incl.x, off);
        unsigned vy = __shfl_up_sync(0xffffffffu, incl.y, off);
        unsigned vz = __shfl_up_sync(0xffffffffu, incl.z, off);
        unsigned vw = __shfl_up_sync(0xffffffffu, incl.w, off);
        if (lane >= off) { incl.x += vx; incl.y += vy; incl.z += vz; incl.w += vw; }
    }

    __shared__ uint4 wtot[32];
    if (lane == 31) wtot[wid] = incl;
    __syncthreads();
    if (wid == 0) {
        uint4 v = wtot[lane];
        uint4 inc2 = v;
        #pragma unroll
        for (int off = 1; off < 32; off <<= 1) {
            unsigned vx = __shfl_up_sync(0xffffffffu, inc2.x, off);
            unsigned vy = __shfl_up_sync(0xffffffffu, inc2.y, off);
            unsigned vz = __shfl_up_sync(0xffffffffu, inc2.z, off);
            unsigned vw = __shfl_up_sync(0xffffffffu, inc2.w, off);
            if (lane >= off) { inc2.x += vx; inc2.y += vy; inc2.z += vz; inc2.w += vw; }
        }
        wtot[lane] = sub4(inc2, v);
    }
    __syncthreads();

    const uint4 base = add4(wtot[wid], sub4(incl, own));
    #pragma unroll
    for (int i = 0; i < 8; i++) {
        uint4 tot = add4(base, pre[i]);
        unsigned word = (unsigned)e[i] >> 1;
        unsigned w = (word == 0) ? tot.x : (word == 1) ? tot.y : (word == 2) ? tot.z : tot.w;
        g_pos[tid * 8 + i] = (int)((w >> ((e[i] & 1) * 16)) & 0xFFFFu);
    }
}

// ---------------- scatter ----------------
__global__ void scatter_kernel(float* __restrict__ dispatch, float* __restrict__ combine)
{
    int n = blockIdx.x * blockDim.x + threadIdx.x;
    if (n >= NSEL) return;
    int p = g_pos[n];
    if (p < CAP) {
        int tok = n >> 1;
        int e = g_flat_idx[n];
        size_t off = ((size_t)tok * NEXP + e) * CAP + p;
        dispatch[off] = 1.0f;
        combine[off] = g_flat_prob[n];
    }
}

// ---------------- aux loss ----------------
__global__ void aux_kernel(const float* __restrict__ probs, float* __restrict__ aux_out)
{
    __shared__ float sh[256];
    const int tid = threadIdx.x;
    float local[NEXP];
    #pragma unroll
    for (int e = 0; e < NEXP; e++) local[e] = 0.f;
    for (int t = tid; t < NTOK; t += 256) {
        #pragma unroll
        for (int e = 0; e < NEXP; e++) local[e] += probs[t * NEXP + e];
    }
    float aux = 0.f;
    for (int e = 0; e < NEXP; e++) {
        sh[tid] = local[e];
        __syncthreads();
        for (int s = 128; s > 0; s >>= 1) {
            if (tid < s) sh[tid] += sh[tid + s];
            __syncthreads();
        }
        if (tid == 0)
            aux += (sh[0] / (float)NTOK) * ((float)g_counts[e] / (float)NSEL) * (float)NEXP;
        __syncthreads();
    }
    if (tid == 0) *aux_out = aux;
}

// ---------------- launch ----------------
extern "C" void kernel_launch(void* const* d_in, const int* in_sizes, int n_in,
                              void* d_out, int out_size)
{
    const float* x  = (const float*)d_in[0];
    const float* W1 = (const float*)d_in[1];
    const float* b1 = (const float*)d_in[2];
    const float* W2 = (const float*)d_in[3];
    const float* b2 = (const float*)d_in[4];

    float* out      = (float*)d_out;
    float* dispatch = out;
    float* combine  = out + DISPATCH_ELEMS;
    float* probs    = out + PROBS_OFF;
    float* aux      = out + AUX_OFF;

    float* d_h;      cudaGetSymbolAddress((void**)&d_h, g_h);
    float* d_logits; cudaGetSymbolAddress((void**)&d_logits, g_logits);

    static bool attr_set = false;
    if (!attr_set) {
        cudaFuncSetAttribute(gemm1_tc, cudaFuncAttributeMaxDynamicSharedMemorySize, GSMEM);
        attr_set = true;
    }

    // 1) GEMM1 on tensor cores (3xTF32 mma.sync) + fused output zeroing
    gemm1_tc<<<GRID_TOTAL, 512, GSMEM>>>(x, W1, b1, d_h,
                                         (float4*)out, (2LL * DISPATCH_ELEMS) / 4);

    // 2) GEMM2
    gemm2_kernel<<<NTOK / 8, 256>>>(d_h, W2, b2, d_logits);

    // 3) softmax + top-2
    topk_kernel<<<NTOK / 256, 256>>>(d_logits, probs);

    // 4) capacity position scan
    scan_kernel<<<1, 1024>>>();

    // 5) scatter
    scatter_kernel<<<NSEL / 256, 256>>>(dispatch, combine);

    // 6) aux loss
    aux_kernel<<<1, 256>>>(probs, aux);
}

// round 6
// speedup vs baseline: 1.1795x; 1.1795x over previous
#include <cuda_runtime.h>
#include <cuda.h>
#include <math.h>
#include <cstdint>

// ---------------- problem constants ----------------
#define NTOK   4096          // B*S
#define HDIM   4096
#define NEXP   8
#define TOPK   2
#define CAP    1536
#define NSEL   (NTOK*TOPK)

#define DISPATCH_ELEMS  ((long long)NTOK*NEXP*CAP)
#define PROBS_OFF       (2LL*DISPATCH_ELEMS)
#define AUX_OFF         (PROBS_OFF + (long long)NTOK*NEXP)

// ---------------- device scratch ----------------
__device__ float g_h[(size_t)NTOK * HDIM];
__device__ float g_logits[NTOK * NEXP];
__device__ int   g_flat_idx[NSEL];
__device__ float g_flat_prob[NSEL];
__device__ int   g_pos[NSEL];
__device__ int   g_counts[NEXP];

// ---------------- helpers ----------------
__device__ __forceinline__ void cpasync16(uint32_t dst, const void* src) {
    asm volatile("cp.async.cg.shared.global [%0], [%1], 16;\n" :: "r"(dst), "l"(src));
}
#define CP_COMMIT() asm volatile("cp.async.commit_group;\n" ::: "memory")
#define CP_WAIT(n)  asm volatile("cp.async.wait_group %0;\n" :: "n"(n) : "memory")

__device__ __forceinline__ uint32_t smem_u32(const void* p) {
    uint32_t a;
    asm("{ .reg .u64 t; cvta.to.shared.u64 t, %1; cvt.u32.u64 %0, t; }" : "=r"(a) : "l"(p));
    return a;
}

__device__ __forceinline__ float tf32_hi(float v) {
    return __uint_as_float(__float_as_uint(v) & 0xFFFFE000u);
}

// mma.sync m16n8k8 tf32: D += A x B, fp32 accum. Base ISA (sm_80+).
__device__ __forceinline__ void mma_tf32(float c[4],
                                         uint32_t a0, uint32_t a1, uint32_t a2, uint32_t a3,
                                         uint32_t b0, uint32_t b1) {
    asm volatile(
        "mma.sync.aligned.m16n8k8.row.col.f32.tf32.tf32.f32 "
        "{%0,%1,%2,%3}, {%4,%5,%6,%7}, {%8,%9}, {%0,%1,%2,%3};"
        : "+f"(c[0]), "+f"(c[1]), "+f"(c[2]), "+f"(c[3])
        : "r"(a0), "r"(a1), "r"(a2), "r"(a3), "r"(b0), "r"(b1));
}

// ---------------- zero output + counters ----------------
__global__ void zero_kernel(float4* __restrict__ p, long long n4) {
    long long i = blockIdx.x * (long long)blockDim.x + threadIdx.x;
    long long stride = gridDim.x * (long long)blockDim.x;
    float4 z = make_float4(0.f, 0.f, 0.f, 0.f);
    for (; i < n4; i += stride) p[i] = z;
    if (blockIdx.x == 0 && threadIdx.x < NEXP) g_counts[threadIdx.x] = 0;
}

// ---------------- GEMM1: h = relu(x @ W1 + b1), 3xTF32 mma.sync ----------------
// Round-4 shape (256 thr, warp tile 64x32) + register fragment double-buffering:
// prefetch next k-step's raw SMEM values while issuing current k-step's MMAs.
#define BM 128
#define BN 128
#define BK 32
#define ASTRIDE 36     // pad 4 -> conflict-free A frag
#define BSTRIDE 136    // pad 8 -> conflict-free B frag
#define ABYTES (BM * ASTRIDE * 4)     // 18432
#define BBYTES (BK * BSTRIDE * 4)     // 17408
#define STAGEBYTES (ABYTES + BBYTES)  // 35840
#define GSMEM (2 * STAGEBYTES)        // 71680

__global__ __launch_bounds__(256) void gemm1_tc(
    const float* __restrict__ A, const float* __restrict__ B,
    const float* __restrict__ bias, float* __restrict__ C)
{
    extern __shared__ float smem[];
    const int tid = threadIdx.x;
    const int warp = tid >> 5, lane = tid & 31;
    const int wm = (warp & 1) * 64;       // warp m-offset
    const int wn = (warp >> 1) * 32;      // warp n-offset
    const int row0 = blockIdx.y * BM;
    const int col0 = blockIdx.x * BN;
    const int r = lane >> 2, cq = lane & 3;

    const uint32_t sb = smem_u32(smem);

    float acc[4][4][4];   // [mtile][ntile][frag]
    #pragma unroll
    for (int i = 0; i < 4; i++)
        #pragma unroll
        for (int j = 0; j < 4; j++)
            #pragma unroll
            for (int f = 0; f < 4; f++) acc[i][j][f] = 0.f;

    auto fill = [&](int buf, int kc) {
        const uint32_t st = sb + buf * STAGEBYTES;
        #pragma unroll
        for (int t = 0; t < 4; t++) {          // A: 1024 x 16B chunks
            int o = tid + t * 256;
            int rr = o >> 3, c16 = o & 7;
            cpasync16(st + (rr * ASTRIDE + c16 * 4) * 4,
                      A + (size_t)(row0 + rr) * HDIM + kc + c16 * 4);
        }
        #pragma unroll
        for (int t = 0; t < 4; t++) {          // B: 1024 x 16B chunks
            int o = tid + t * 256;
            int rr = o >> 5, c16 = o & 31;
            cpasync16(st + ABYTES + (rr * BSTRIDE + c16 * 4) * 4,
                      B + (size_t)(kc + rr) * HDIM + col0 + c16 * 4);
        }
    };

    fill(0, 0);
    CP_COMMIT();

    const int NCHUNK = HDIM / BK;   // 128
    for (int c = 0; c < NCHUNK; ++c) {
        if (c + 1 < NCHUNK) { fill((c + 1) & 1, (c + 1) * BK); CP_COMMIT(); CP_WAIT(1); }
        else                { CP_WAIT(0); }
        __syncthreads();

        const float* As = smem + ((c & 1) * STAGEBYTES) / 4;
        const float* Bs = As + ABYTES / 4;

        // raw fragment double buffers (register-resident)
        float ar[2][4][4], br[2][4][2];

        // preload k-step 0 raw values
        #pragma unroll
        for (int mt = 0; mt < 4; mt++) {
            const float* pa = As + (size_t)(wm + mt * 16 + r) * ASTRIDE + cq;
            ar[0][mt][0] = pa[0];
            ar[0][mt][1] = pa[8 * ASTRIDE];
            ar[0][mt][2] = pa[4];
            ar[0][mt][3] = pa[8 * ASTRIDE + 4];
        }
        #pragma unroll
        for (int nt = 0; nt < 4; nt++) {
            const float* pb = Bs + (size_t)cq * BSTRIDE + wn + nt * 8 + r;
            br[0][nt][0] = pb[0];
            br[0][nt][1] = pb[4 * BSTRIDE];
        }

        #pragma unroll
        for (int ks = 0; ks < 4; ks++) {
            const int cur = ks & 1, nxt = cur ^ 1;

            // prefetch next k-step raw values FIRST (hides LDS latency under MMAs)
            if (ks < 3) {
                const int kk = (ks + 1) * 8;
                #pragma unroll
                for (int mt = 0; mt < 4; mt++) {
                    const float* pa = As + (size_t)(wm + mt * 16 + r) * ASTRIDE + kk + cq;
                    ar[nxt][mt][0] = pa[0];
                    ar[nxt][mt][1] = pa[8 * ASTRIDE];
                    ar[nxt][mt][2] = pa[4];
                    ar[nxt][mt][3] = pa[8 * ASTRIDE + 4];
                }
                #pragma unroll
                for (int nt = 0; nt < 4; nt++) {
                    const float* pb = Bs + (size_t)(kk + cq) * BSTRIDE + wn + nt * 8 + r;
                    br[nxt][nt][0] = pb[0];
                    br[nxt][nt][1] = pb[4 * BSTRIDE];
                }
            }

            // split current k-step in registers
            // A frags (m16n8k8 tf32): a0=(r,cq) a1=(r+8,cq) a2=(r,cq+4) a3=(r+8,cq+4)
            uint32_t ahi[4][4], alo[4][4];
            #pragma unroll
            for (int mt = 0; mt < 4; mt++)
                #pragma unroll
                for (int f = 0; f < 4; f++) {
                    float a = ar[cur][mt][f];
                    float h = tf32_hi(a);
                    ahi[mt][f] = __float_as_uint(h);
                    alo[mt][f] = __float_as_uint(a - h);
                }
            uint32_t bhi[4][2], blo[4][2];
            #pragma unroll
            for (int nt = 0; nt < 4; nt++)
                #pragma unroll
                for (int f = 0; f < 2; f++) {
                    float b = br[cur][nt][f];
                    float h = tf32_hi(b);
                    bhi[nt][f] = __float_as_uint(h);
                    blo[nt][f] = __float_as_uint(b - h);
                }

            // 3x-split mma (48 HMMAs)
            #pragma unroll
            for (int mt = 0; mt < 4; mt++)
                #pragma unroll
                for (int nt = 0; nt < 4; nt++) {
                    mma_tf32(acc[mt][nt], ahi[mt][0], ahi[mt][1], ahi[mt][2], ahi[mt][3],
                             bhi[nt][0], bhi[nt][1]);
                    mma_tf32(acc[mt][nt], ahi[mt][0], ahi[mt][1], ahi[mt][2], ahi[mt][3],
                             blo[nt][0], blo[nt][1]);
                    mma_tf32(acc[mt][nt], alo[mt][0], alo[mt][1], alo[mt][2], alo[mt][3],
                             bhi[nt][0], bhi[nt][1]);
                }
        }
        __syncthreads();
    }

    // ---- epilogue: relu(acc + bias) -> C ----
    // C frag: c0=(r, 2cq) c1=(r, 2cq+1) c2=(r+8, 2cq) c3=(r+8, 2cq+1)
    #pragma unroll
    for (int mt = 0; mt < 4; mt++) {
        #pragma unroll
        for (int nt = 0; nt < 4; nt++) {
            int col = col0 + wn + nt * 8 + 2 * cq;
            float bx = __ldg(bias + col), by = __ldg(bias + col + 1);
            int rowa = row0 + wm + mt * 16 + r;
            float2 v0, v1;
            v0.x = fmaxf(acc[mt][nt][0] + bx, 0.f);
            v0.y = fmaxf(acc[mt][nt][1] + by, 0.f);
            v1.x = fmaxf(acc[mt][nt][2] + bx, 0.f);
            v1.y = fmaxf(acc[mt][nt][3] + by, 0.f);
            *(float2*)(C + (size_t)rowa * HDIM + col) = v0;
            *(float2*)(C + (size_t)(rowa + 8) * HDIM + col) = v1;
        }
    }
}

// ---------------- GEMM2: logits = h @ W2 + b2 (one warp per token) ----------------
__global__ void gemm2_kernel(const float* __restrict__ h, const float* __restrict__ W2,
                             const float* __restrict__ b2, float* __restrict__ logits)
{
    int warp = (blockIdx.x * blockDim.x + threadIdx.x) >> 5;
    int lane = threadIdx.x & 31;
    if (warp >= NTOK) return;
    const float* hr = h + (size_t)warp * HDIM;

    float acc[NEXP];
    #pragma unroll
    for (int e = 0; e < NEXP; e++) acc[e] = 0.f;

    for (int k0 = lane * 4; k0 < HDIM; k0 += 128) {
        float4 hv = *(const float4*)(hr + k0);
        float hvv[4] = {hv.x, hv.y, hv.z, hv.w};
        #pragma unroll
        for (int j = 0; j < 4; j++) {
            const float* w = W2 + (size_t)(k0 + j) * NEXP;
            float4 w0 = *(const float4*)w;
            float4 w1 = *(const float4*)(w + 4);
            acc[0] += hvv[j] * w0.x; acc[1] += hvv[j] * w0.y;
            acc[2] += hvv[j] * w0.z; acc[3] += hvv[j] * w0.w;
            acc[4] += hvv[j] * w1.x; acc[5] += hvv[j] * w1.y;
            acc[6] += hvv[j] * w1.z; acc[7] += hvv[j] * w1.w;
        }
    }
    #pragma unroll
    for (int e = 0; e < NEXP; e++) {
        #pragma unroll
        for (int off = 16; off > 0; off >>= 1)
            acc[e] += __shfl_down_sync(0xffffffffu, acc[e], off);
    }
    if (lane == 0) {
        #pragma unroll
        for (int e = 0; e < NEXP; e++)
            logits[warp * NEXP + e] = acc[e] + b2[e];
    }
}

// ---------------- softmax + top-2 ----------------
__global__ void topk_kernel(const float* __restrict__ logits, float* __restrict__ probs_out)
{
    int t = blockIdx.x * blockDim.x + threadIdx.x;
    if (t >= NTOK) return;
    float l[NEXP];
    float m = -1e30f;
    #pragma unroll
    for (int e = 0; e < NEXP; e++) { l[e] = logits[t * NEXP + e]; m = fmaxf(m, l[e]); }
    float s = 0.f;
    #pragma unroll
    for (int e = 0; e < NEXP; e++) { l[e] = expf(l[e] - m); s += l[e]; }
    float inv = 1.f / s;
    float p[NEXP];
    #pragma unroll
    for (int e = 0; e < NEXP; e++) { p[e] = l[e] * inv; probs_out[t * NEXP + e] = p[e]; }

    int i1 = 0; float p1 = p[0];
    #pragma unroll
    for (int e = 1; e < NEXP; e++) if (p[e] > p1) { p1 = p[e]; i1 = e; }
    int i2 = -1; float p2 = -1.f;
    #pragma unroll
    for (int e = 0; e < NEXP; e++) if (e != i1 && p[e] > p2) { p2 = p[e]; i2 = e; }

    float norm = 1.f / (p1 + p2 + 1e-8f);
    g_flat_idx[2 * t + 0] = i1;
    g_flat_idx[2 * t + 1] = i2;
    g_flat_prob[2 * t + 0] = p1 * norm;
    g_flat_prob[2 * t + 1] = p2 * norm;
    atomicAdd(&g_counts[i1], 1);
    atomicAdd(&g_counts[i2], 1);
}

// ---------------- exclusive per-expert position scan ----------------
__device__ __forceinline__ uint4 add4(uint4 a, uint4 b) {
    return make_uint4(a.x + b.x, a.y + b.y, a.z + b.z, a.w + b.w);
}
__device__ __forceinline__ uint4 sub4(uint4 a, uint4 b) {
    return make_uint4(a.x - b.x, a.y - b.y, a.z - b.z, a.w - b.w);
}
__global__ __launch_bounds__(1024) void scan_kernel()
{
    const int tid = threadIdx.x;
    const int lane = tid & 31, wid = tid >> 5;

    int e[8];
    uint4 pre[8];
    uint4 run = make_uint4(0, 0, 0, 0);
    #pragma unroll
    for (int i = 0; i < 8; i++) {
        e[i] = g_flat_idx[tid * 8 + i];
        pre[i] = run;
        unsigned word = (unsigned)e[i] >> 1;
        unsigned add = 1u << ((e[i] & 1) * 16);
        if (word == 0) run.x += add;
        else if (word == 1) run.y += add;
        else if (word == 2) run.z += add;
        else run.w += add;
    }
    const uint4 own = run;

    uint4 incl = own;
    #pragma unroll
    for (int off = 1; off < 32; off <<= 1) {
        unsigned vx = __shfl_up_sync(0xffffffffu, incl.x, off);
        unsigned vy = __shfl_up_sync(0xffffffffu, incl.y, off);
        unsigned vz = __shfl_up_sync(0xffffffffu, incl.z, off);
        unsigned vw = __shfl_up_sync(0xffffffffu, incl.w, off);
        if (lane >= off) { incl.x += vx; incl.y += vy; incl.z += vz; incl.w += vw; }
    }

    __shared__ uint4 wtot[32];
    if (lane == 31) wtot[wid] = incl;
    __syncthreads();
    if (wid == 0) {
        uint4 v = wtot[lane];
        uint4 inc2 = v;
        #pragma unroll
        for (int off = 1; off < 32; off <<= 1) {
            unsigned vx = __shfl_up_sync(0xffffffffu, inc2.x, off);
            unsigned vy = __shfl_up_sync(0xffffffffu, inc2.y, off);
            unsigned vz = __shfl_up_sync(0xffffffffu, inc2.z, off);
            unsigned vw = __shfl_up_sync(0xffffffffu, inc2.w, off);
            if (lane >= off) { inc2.x += vx; inc2.y += vy; inc2.z += vz; inc2.w += vw; }
        }
        wtot[lane] = sub4(inc2, v);
    }
    __syncthreads();

    const uint4 base = add4(wtot[wid], sub4(incl, own));
    #pragma unroll
    for (int i = 0; i < 8; i++) {
        uint4 tot = add4(base, pre[i]);
        unsigned word = (unsigned)e[i] >> 1;
        unsigned w = (word == 0) ? tot.x : (word == 1) ? tot.y : (word == 2) ? tot.z : tot.w;
        g_pos[tid * 8 + i] = (int)((w >> ((e[i] & 1) * 16)) & 0xFFFFu);
    }
}

// ---------------- scatter ----------------
__global__ void scatter_kernel(float* __restrict__ dispatch, float* __restrict__ combine)
{
    int n = blockIdx.x * blockDim.x + threadIdx.x;
    if (n >= NSEL) return;
    int p = g_pos[n];
    if (p < CAP) {
        int tok = n >> 1;
        int e = g_flat_idx[n];
        size_t off = ((size_t)tok * NEXP + e) * CAP + p;
        dispatch[off] = 1.0f;
        combine[off] = g_flat_prob[n];
    }
}

// ---------------- aux loss ----------------
__global__ void aux_kernel(const float* __restrict__ probs, float* __restrict__ aux_out)
{
    __shared__ float sh[256];
    const int tid = threadIdx.x;
    float local[NEXP];
    #pragma unroll
    for (int e = 0; e < NEXP; e++) local[e] = 0.f;
    for (int t = tid; t < NTOK; t += 256) {
        #pragma unroll
        for (int e = 0; e < NEXP; e++) local[e] += probs[t * NEXP + e];
    }
    float aux = 0.f;
    for (int e = 0; e < NEXP; e++) {
        sh[tid] = local[e];
        __syncthreads();
        for (int s = 128; s > 0; s >>= 1) {
            if (tid < s) sh[tid] += sh[tid + s];
            __syncthreads();
        }
        if (tid == 0)
            aux += (sh[0] / (float)NTOK) * ((float)g_counts[e] / (float)NSEL) * (float)NEXP;
        __syncthreads();
    }
    if (tid == 0) *aux_out = aux;
}

// ---------------- launch ----------------
extern "C" void kernel_launch(void* const* d_in, const int* in_sizes, int n_in,
                              void* d_out, int out_size)
{
    const float* x  = (const float*)d_in[0];
    const float* W1 = (const float*)d_in[1];
    const float* b1 = (const float*)d_in[2];
    const float* W2 = (const float*)d_in[3];
    const float* b2 = (const float*)d_in[4];

    float* out      = (float*)d_out;
    float* dispatch = out;
    float* combine  = out + DISPATCH_ELEMS;
    float* probs    = out + PROBS_OFF;
    float* aux      = out + AUX_OFF;

    float* d_h;      cudaGetSymbolAddress((void**)&d_h, g_h);
    float* d_logits; cudaGetSymbolAddress((void**)&d_logits, g_logits);

    static bool attr_set = false;
    if (!attr_set) {
        cudaFuncSetAttribute(gemm1_tc, cudaFuncAttributeMaxDynamicSharedMemorySize, GSMEM);
        attr_set = true;
    }

    // 1) zero dispatch + combine (+ counters)
    zero_kernel<<<4096, 256>>>((float4*)out, (2LL * DISPATCH_ELEMS) / 4);

    // 2) GEMM1 on tensor cores (3xTF32 mma.sync, reg-pipelined)
    gemm1_tc<<<dim3(HDIM / BN, NTOK / BM), 256, GSMEM>>>(x, W1, b1, d_h);

    // 3) GEMM2
    gemm2_kernel<<<NTOK / 8, 256>>>(d_h, W2, b2, d_logits);

    // 4) softmax + top-2
    topk_kernel<<<NTOK / 256, 256>>>(d_logits, probs);

    // 5) capacity position scan
    scan_kernel<<<1, 1024>>>();

    // 6) scatter
    scatter_kernel<<<NSEL / 256, 256>>>(dispatch, combine);

    // 7) aux loss
    aux_kernel<<<1, 256>>>(probs, aux);
}

// round 7
// speedup vs baseline: 1.2457x; 1.0562x over previous
#include <cuda_runtime.h>
#include <cuda.h>
#include <math.h>
#include <cstdint>

// ---------------- problem constants ----------------
#define NTOK   4096          // B*S
#define HDIM   4096
#define NEXP   8
#define TOPK   2
#define CAP    1536
#define NSEL   (NTOK*TOPK)

#define DISPATCH_ELEMS  ((long long)NTOK*NEXP*CAP)
#define PROBS_OFF       (2LL*DISPATCH_ELEMS)
#define AUX_OFF         (PROBS_OFF + (long long)NTOK*NEXP)

// ---------------- device scratch ----------------
__device__ float g_h[(size_t)NTOK * HDIM];
__device__ float g_logits[NTOK * NEXP];
__device__ int   g_flat_idx[NSEL];
__device__ float g_flat_prob[NSEL];
__device__ int   g_pos[NSEL];
__device__ int   g_counts[NEXP];

// ---------------- helpers ----------------
__device__ __forceinline__ void cpasync16(uint32_t dst, const void* src) {
    asm volatile("cp.async.cg.shared.global [%0], [%1], 16;\n" :: "r"(dst), "l"(src));
}
#define CP_COMMIT() asm volatile("cp.async.commit_group;\n" ::: "memory")
#define CP_WAIT(n)  asm volatile("cp.async.wait_group %0;\n" :: "n"(n) : "memory")

__device__ __forceinline__ uint32_t smem_u32(const void* p) {
    uint32_t a;
    asm("{ .reg .u64 t; cvta.to.shared.u64 t, %1; cvt.u32.u64 %0, t; }" : "=r"(a) : "l"(p));
    return a;
}

__device__ __forceinline__ float tf32_hi(float v) {
    return __uint_as_float(__float_as_uint(v) & 0xFFFFE000u);
}

// mma.sync m16n8k8 tf32: D += A x B, fp32 accum. Base ISA (sm_80+).
__device__ __forceinline__ void mma_tf32(float c[4],
                                         uint32_t a0, uint32_t a1, uint32_t a2, uint32_t a3,
                                         uint32_t b0, uint32_t b1) {
    asm volatile(
        "mma.sync.aligned.m16n8k8.row.col.f32.tf32.tf32.f32 "
        "{%0,%1,%2,%3}, {%4,%5,%6,%7}, {%8,%9}, {%0,%1,%2,%3};"
        : "+f"(c[0]), "+f"(c[1]), "+f"(c[2]), "+f"(c[3])
        : "r"(a0), "r"(a1), "r"(a2), "r"(a3), "r"(b0), "r"(b1));
}

// ---------------- GEMM1: h = relu(x @ W1 + b1), 3xTF32 mma.sync ----------------
// Round-4 shape (256 thr, warp tile 64x32). Changes vs round-4:
//  * split products issued in 3 passes (hh, hl, lh) -> same-acc MMAs 16 apart
//  * output zeroing fused in: 1 float4 zero-store per thread per chunk (c<96)
#define BM 128
#define BN 128
#define BK 32
#define ASTRIDE 36     // pad 4 -> conflict-free A frag
#define BSTRIDE 136    // pad 8 -> conflict-free B frag
#define ABYTES (BM * ASTRIDE * 4)     // 18432
#define BBYTES (BK * BSTRIDE * 4)     // 17408
#define STAGEBYTES (ABYTES + BBYTES)  // 35840
#define GSMEM (2 * STAGEBYTES)        // 71680
#define ZPT 96                        // zero-chunks per CTA (96*256 float4 = 98304 floats)

__global__ __launch_bounds__(256) void gemm1_tc(
    const float* __restrict__ A, const float* __restrict__ B,
    const float* __restrict__ bias, float* __restrict__ C,
    float4* __restrict__ zout)
{
    extern __shared__ float smem[];
    const int tid = threadIdx.x;
    const int warp = tid >> 5, lane = tid & 31;
    const int wm = (warp & 1) * 64;       // warp m-offset
    const int wn = (warp >> 1) * 32;      // warp n-offset
    const int row0 = blockIdx.y * BM;
    const int col0 = blockIdx.x * BN;
    const int r = lane >> 2, cq = lane & 3;
    const int ctalin = blockIdx.y * 32 + blockIdx.x;   // 0..1023

    const uint32_t sb = smem_u32(smem);

    if (ctalin == 0 && tid < NEXP) g_counts[tid] = 0;

    float acc[4][4][4];   // [mtile][ntile][frag]
    #pragma unroll
    for (int i = 0; i < 4; i++)
        #pragma unroll
        for (int j = 0; j < 4; j++)
            #pragma unroll
            for (int f = 0; f < 4; f++) acc[i][j][f] = 0.f;

    auto fill = [&](int buf, int kc) {
        const uint32_t st = sb + buf * STAGEBYTES;
        #pragma unroll
        for (int t = 0; t < 4; t++) {          // A: 1024 x 16B chunks
            int o = tid + t * 256;
            int rr = o >> 3, c16 = o & 7;
            cpasync16(st + (rr * ASTRIDE + c16 * 4) * 4,
                      A + (size_t)(row0 + rr) * HDIM + kc + c16 * 4);
        }
        #pragma unroll
        for (int t = 0; t < 4; t++) {          // B: 1024 x 16B chunks
            int o = tid + t * 256;
            int rr = o >> 5, c16 = o & 31;
            cpasync16(st + ABYTES + (rr * BSTRIDE + c16 * 4) * 4,
                      B + (size_t)(kc + rr) * HDIM + col0 + c16 * 4);
        }
    };

    fill(0, 0);
    CP_COMMIT();

    const float4 z4 = make_float4(0.f, 0.f, 0.f, 0.f);
    const long long zbase = (long long)ctalin * (ZPT * 256) + tid;

    const int NCHUNK = HDIM / BK;   // 128
    for (int c = 0; c < NCHUNK; ++c) {
        // fused output zeroing: hidden under the compute-bound mainloop
        if (c < ZPT) zout[zbase + (long long)c * 256] = z4;

        if (c + 1 < NCHUNK) { fill((c + 1) & 1, (c + 1) * BK); CP_COMMIT(); CP_WAIT(1); }
        else                { CP_WAIT(0); }
        __syncthreads();

        const float* As = smem + ((c & 1) * STAGEBYTES) / 4;
        const float* Bs = As + ABYTES / 4;

        #pragma unroll
        for (int kk = 0; kk < BK; kk += 8) {
            // A frags (m16n8k8 tf32): a0=(r,cq) a1=(r+8,cq) a2=(r,cq+4) a3=(r+8,cq+4)
            uint32_t ahi[4][4], alo[4][4];
            #pragma unroll
            for (int mt = 0; mt < 4; mt++) {
                const float* pa = As + (size_t)(wm + mt * 16 + r) * ASTRIDE + kk + cq;
                float a0 = pa[0];
                float a1 = pa[8 * ASTRIDE];
                float a2 = pa[4];
                float a3 = pa[8 * ASTRIDE + 4];
                float h0 = tf32_hi(a0), h1 = tf32_hi(a1), h2 = tf32_hi(a2), h3 = tf32_hi(a3);
                ahi[mt][0] = __float_as_uint(h0); alo[mt][0] = __float_as_uint(a0 - h0);
                ahi[mt][1] = __float_as_uint(h1); alo[mt][1] = __float_as_uint(a1 - h1);
                ahi[mt][2] = __float_as_uint(h2); alo[mt][2] = __float_as_uint(a2 - h2);
                ahi[mt][3] = __float_as_uint(h3); alo[mt][3] = __float_as_uint(a3 - h3);
            }
            // B frags: b0=(k=cq, n=r), b1=(k=cq+4, n=r)
            uint32_t bhi[4][2], blo[4][2];
            #pragma unroll
            for (int nt = 0; nt < 4; nt++) {
                const float* pb = Bs + (size_t)(kk + cq) * BSTRIDE + wn + nt * 8 + r;
                float b0 = pb[0], b1 = pb[4 * BSTRIDE];
                float h0 = tf32_hi(b0), h1 = tf32_hi(b1);
                bhi[nt][0] = __float_as_uint(h0); blo[nt][0] = __float_as_uint(b0 - h0);
                bhi[nt][1] = __float_as_uint(h1); blo[nt][1] = __float_as_uint(b1 - h1);
            }
            // 3 passes: same-acc MMAs spaced 16 apart (RAW-chain relief).
            // Per-acc accumulation order stays hh -> hl -> lh (numerics identical).
            #pragma unroll
            for (int mt = 0; mt < 4; mt++)
                #pragma unroll
                for (int nt = 0; nt < 4; nt++)
                    mma_tf32(acc[mt][nt], ahi[mt][0], ahi[mt][1], ahi[mt][2], ahi[mt][3],
                             bhi[nt][0], bhi[nt][1]);
            #pragma unroll
            for (int mt = 0; mt < 4; mt++)
                #pragma unroll
                for (int nt = 0; nt < 4; nt++)
                    mma_tf32(acc[mt][nt], ahi[mt][0], ahi[mt][1], ahi[mt][2], ahi[mt][3],
                             blo[nt][0], blo[nt][1]);
            #pragma unroll
            for (int mt = 0; mt < 4; mt++)
                #pragma unroll
                for (int nt = 0; nt < 4; nt++)
                    mma_tf32(acc[mt][nt], alo[mt][0], alo[mt][1], alo[mt][2], alo[mt][3],
                             bhi[nt][0], bhi[nt][1]);
        }
        __syncthreads();
    }

    // ---- epilogue: relu(acc + bias) -> C ----
    // C frag: c0=(r, 2cq) c1=(r, 2cq+1) c2=(r+8, 2cq) c3=(r+8, 2cq+1)
    #pragma unroll
    for (int mt = 0; mt < 4; mt++) {
        #pragma unroll
        for (int nt = 0; nt < 4; nt++) {
            int col = col0 + wn + nt * 8 + 2 * cq;
            float bx = __ldg(bias + col), by = __ldg(bias + col + 1);
            int rowa = row0 + wm + mt * 16 + r;
            float2 v0, v1;
            v0.x = fmaxf(acc[mt][nt][0] + bx, 0.f);
            v0.y = fmaxf(acc[mt][nt][1] + by, 0.f);
            v1.x = fmaxf(acc[mt][nt][2] + bx, 0.f);
            v1.y = fmaxf(acc[mt][nt][3] + by, 0.f);
            *(float2*)(C + (size_t)rowa * HDIM + col) = v0;
            *(float2*)(C + (size_t)(rowa + 8) * HDIM + col) = v1;
        }
    }
}

// ---------------- GEMM2: logits = h @ W2 + b2 (one warp per token) ----------------
__global__ void gemm2_kernel(const float* __restrict__ h, const float* __restrict__ W2,
                             const float* __restrict__ b2, float* __restrict__ logits)
{
    int warp = (blockIdx.x * blockDim.x + threadIdx.x) >> 5;
    int lane = threadIdx.x & 31;
    if (warp >= NTOK) return;
    const float* hr = h + (size_t)warp * HDIM;

    float acc[NEXP];
    #pragma unroll
    for (int e = 0; e < NEXP; e++) acc[e] = 0.f;

    for (int k0 = lane * 4; k0 < HDIM; k0 += 128) {
        float4 hv = *(const float4*)(hr + k0);
        float hvv[4] = {hv.x, hv.y, hv.z, hv.w};
        #pragma unroll
        for (int j = 0; j < 4; j++) {
            const float* w = W2 + (size_t)(k0 + j) * NEXP;
            float4 w0 = *(const float4*)w;
            float4 w1 = *(const float4*)(w + 4);
            acc[0] += hvv[j] * w0.x; acc[1] += hvv[j] * w0.y;
            acc[2] += hvv[j] * w0.z; acc[3] += hvv[j] * w0.w;
            acc[4] += hvv[j] * w1.x; acc[5] += hvv[j] * w1.y;
            acc[6] += hvv[j] * w1.z; acc[7] += hvv[j] * w1.w;
        }
    }
    #pragma unroll
    for (int e = 0; e < NEXP; e++) {
        #pragma unroll
        for (int off = 16; off > 0; off >>= 1)
            acc[e] += __shfl_down_sync(0xffffffffu, acc[e], off);
    }
    if (lane == 0) {
        #pragma unroll
        for (int e = 0; e < NEXP; e++)
            logits[warp * NEXP + e] = acc[e] + b2[e];
    }
}

// ---------------- softmax + top-2 ----------------
__global__ void topk_kernel(const float* __restrict__ logits, float* __restrict__ probs_out)
{
    int t = blockIdx.x * blockDim.x + threadIdx.x;
    if (t >= NTOK) return;
    float l[NEXP];
    float m = -1e30f;
    #pragma unroll
    for (int e = 0; e < NEXP; e++) { l[e] = logits[t * NEXP + e]; m = fmaxf(m, l[e]); }
    float s = 0.f;
    #pragma unroll
    for (int e = 0; e < NEXP; e++) { l[e] = expf(l[e] - m); s += l[e]; }
    float inv = 1.f / s;
    float p[NEXP];
    #pragma unroll
    for (int e = 0; e < NEXP; e++) { p[e] = l[e] * inv; probs_out[t * NEXP + e] = p[e]; }

    int i1 = 0; float p1 = p[0];
    #pragma unroll
    for (int e = 1; e < NEXP; e++) if (p[e] > p1) { p1 = p[e]; i1 = e; }
    int i2 = -1; float p2 = -1.f;
    #pragma unroll
    for (int e = 0; e < NEXP; e++) if (e != i1 && p[e] > p2) { p2 = p[e]; i2 = e; }

    float norm = 1.f / (p1 + p2 + 1e-8f);
    g_flat_idx[2 * t + 0] = i1;
    g_flat_idx[2 * t + 1] = i2;
    g_flat_prob[2 * t + 0] = p1 * norm;
    g_flat_prob[2 * t + 1] = p2 * norm;
    atomicAdd(&g_counts[i1], 1);
    atomicAdd(&g_counts[i2], 1);
}

// ---------------- exclusive per-expert position scan ----------------
__device__ __forceinline__ uint4 add4(uint4 a, uint4 b) {
    return make_uint4(a.x + b.x, a.y + b.y, a.z + b.z, a.w + b.w);
}
__device__ __forceinline__ uint4 sub4(uint4 a, uint4 b) {
    return make_uint4(a.x - b.x, a.y - b.y, a.z - b.z, a.w - b.w);
}
__global__ __launch_bounds__(1024) void scan_kernel()
{
    const int tid = threadIdx.x;
    const int lane = tid & 31, wid = tid >> 5;

    int e[8];
    uint4 pre[8];
    uint4 run = make_uint4(0, 0, 0, 0);
    #pragma unroll
    for (int i = 0; i < 8; i++) {
        e[i] = g_flat_idx[tid * 8 + i];
        pre[i] = run;
        unsigned word = (unsigned)e[i] >> 1;
        unsigned add = 1u << ((e[i] & 1) * 16);
        if (word == 0) run.x += add;
        else if (word == 1) run.y += add;
        else if (word == 2) run.z += add;
        else run.w += add;
    }
    const uint4 own = run;

    uint4 incl = own;
    #pragma unroll
    for (int off = 1; off < 32; off <<= 1) {
        unsigned vx = __shfl_up_sync(0xffffffffu, incl.x, off);
        unsigned vy = __shfl_up_sync(0xffffffffu, incl.y, off);
        unsigned vz = __shfl_up_sync(0xffffffffu, incl.z, off);
        unsigned vw = __shfl_up_sync(0xffffffffu, incl.w, off);
        if (lane >= off) { incl.x += vx; incl.y += vy; incl.z += vz; incl.w += vw; }
    }

    __shared__ uint4 wtot[32];
    if (lane == 31) wtot[wid] = incl;
    __syncthreads();
    if (wid == 0) {
        uint4 v = wtot[lane];
        uint4 inc2 = v;
        #pragma unroll
        for (int off = 1; off < 32; off <<= 1) {
            unsigned vx = __shfl_up_sync(0xffffffffu, inc2.x, off);
            unsigned vy = __shfl_up_sync(0xffffffffu, inc2.y, off);
            unsigned vz = __shfl_up_sync(0xffffffffu, inc2.z, off);
            unsigned vw = __shfl_up_sync(0xffffffffu, inc2.w, off);
            if (lane >= off) { inc2.x += vx; inc2.y += vy; inc2.z += vz; inc2.w += vw; }
        }
        wtot[lane] = sub4(inc2, v);
    }
    __syncthreads();

    const uint4 base = add4(wtot[wid], sub4(incl, own));
    #pragma unroll
    for (int i = 0; i < 8; i++) {
        uint4 tot = add4(base, pre[i]);
        unsigned word = (unsigned)e[i] >> 1;
        unsigned w = (word == 0) ? tot.x : (word == 1) ? tot.y : (word == 2) ? tot.z : tot.w;
        g_pos[tid * 8 + i] = (int)((w >> ((e[i] & 1) * 16)) & 0xFFFFu);
    }
}

// ---------------- scatter ----------------
__global__ void scatter_kernel(float* __restrict__ dispatch, float* __restrict__ combine)
{
    int n = blockIdx.x * blockDim.x + threadIdx.x;
    if (n >= NSEL) return;
    int p = g_pos[n];
    if (p < CAP) {
        int tok = n >> 1;
        int e = g_flat_idx[n];
        size_t off = ((size_t)tok * NEXP + e) * CAP + p;
        dispatch[off] = 1.0f;
        combine[off] = g_flat_prob[n];
    }
}

// ---------------- aux loss ----------------
__global__ void aux_kernel(const float* __restrict__ probs, float* __restrict__ aux_out)
{
    __shared__ float sh[256];
    const int tid = threadIdx.x;
    float local[NEXP];
    #pragma unroll
    for (int e = 0; e < NEXP; e++) local[e] = 0.f;
    for (int t = tid; t < NTOK; t += 256) {
        #pragma unroll
        for (int e = 0; e < NEXP; e++) local[e] += probs[t * NEXP + e];
    }
    float aux = 0.f;
    for (int e = 0; e < NEXP; e++) {
        sh[tid] = local[e];
        __syncthreads();
        for (int s = 128; s > 0; s >>= 1) {
            if (tid < s) sh[tid] += sh[tid + s];
            __syncthreads();
        }
        if (tid == 0)
            aux += (sh[0] / (float)NTOK) * ((float)g_counts[e] / (float)NSEL) * (float)NEXP;
        __syncthreads();
    }
    if (tid == 0) *aux_out = aux;
}

// ---------------- launch ----------------
extern "C" void kernel_launch(void* const* d_in, const int* in_sizes, int n_in,
                              void* d_out, int out_size)
{
    const float* x  = (const float*)d_in[0];
    const float* W1 = (const float*)d_in[1];
    const float* b1 = (const float*)d_in[2];
    const float* W2 = (const float*)d_in[3];
    const float* b2 = (const float*)d_in[4];

    float* out      = (float*)d_out;
    float* dispatch = out;
    float* combine  = out + DISPATCH_ELEMS;
    float* probs    = out + PROBS_OFF;
    float* aux      = out + AUX_OFF;

    float* d_h;      cudaGetSymbolAddress((void**)&d_h, g_h);
    float* d_logits; cudaGetSymbolAddress((void**)&d_logits, g_logits);

    static bool attr_set = false;
    if (!attr_set) {
        cudaFuncSetAttribute(gemm1_tc, cudaFuncAttributeMaxDynamicSharedMemorySize, GSMEM);
        attr_set = true;
    }

    // 1) GEMM1 (3xTF32 mma.sync, split-pass-reordered) + fused output zeroing
    gemm1_tc<<<dim3(HDIM / BN, NTOK / BM), 256, GSMEM>>>(x, W1, b1, d_h, (float4*)out);

    // 2) GEMM2
    gemm2_kernel<<<NTOK / 8, 256>>>(d_h, W2, b2, d_logits);

    // 3) softmax + top-2
    topk_kernel<<<NTOK / 256, 256>>>(d_logits, probs);

    // 4) capacity position scan
    scan_kernel<<<1, 1024>>>();

    // 5) scatter
    scatter_kernel<<<NSEL / 256, 256>>>(dispatch, combine);

    // 6) aux loss
    aux_kernel<<<1, 256>>>(probs, aux);
}

// round 8
// speedup vs baseline: 1.4746x; 1.1837x over previous
#include <cuda_runtime.h>
#include <cuda.h>
#include <math.h>
#include <cstdint>

// ---------------- problem constants ----------------
#define NTOK   4096          // B*S
#define HDIM   4096
#define NEXP   8
#define TOPK   2
#define CAP    1536
#define NSEL   (NTOK*TOPK)

#define DISPATCH_ELEMS  ((long long)NTOK*NEXP*CAP)
#define PROBS_OFF       (2LL*DISPATCH_ELEMS)
#define AUX_OFF         (PROBS_OFF + (long long)NTOK*NEXP)

// ---------------- device scratch ----------------
__device__ float g_h[(size_t)NTOK * HDIM];
__device__ float g_logits[NTOK * NEXP];
__device__ int   g_flat_idx[NSEL];
__device__ float g_flat_prob[NSEL];
__device__ int   g_pos[NSEL];
__device__ int   g_counts[NEXP];

// ---------------- helpers ----------------
__device__ __forceinline__ void cpasync16(uint32_t dst, const void* src) {
    asm volatile("cp.async.cg.shared.global [%0], [%1], 16;\n" :: "r"(dst), "l"(src));
}
#define CP_COMMIT() asm volatile("cp.async.commit_group;\n" ::: "memory")
#define CP_WAIT(n)  asm volatile("cp.async.wait_group %0;\n" :: "n"(n) : "memory")

__device__ __forceinline__ uint32_t smem_u32(const void* p) {
    uint32_t a;
    asm("{ .reg .u64 t; cvta.to.shared.u64 t, %1; cvt.u32.u64 %0, t; }" : "=r"(a) : "l"(p));
    return a;
}

// keep top 10 explicit mantissa bits (exactly fp16-representable in normal range)
__device__ __forceinline__ float hi10(float v) {
    return __uint_as_float(__float_as_uint(v) & 0xFFFFE000u);
}
// pack {lo-half = eve, hi-half = odd} as f16x2 (first PTX source -> high half)
__device__ __forceinline__ uint32_t pk(float eve, float odd) {
    uint32_t d;
    asm("cvt.rn.f16x2.f32 %0, %1, %2;" : "=r"(d) : "f"(odd), "f"(eve));
    return d;
}

// mma.sync m16n8k16 fp16 inputs, fp32 accum. Base ISA (sm_80+).
__device__ __forceinline__ void mma_f16(float c[4],
                                        uint32_t a0, uint32_t a1, uint32_t a2, uint32_t a3,
                                        uint32_t b0, uint32_t b1) {
    asm volatile(
        "mma.sync.aligned.m16n8k16.row.col.f32.f16.f16.f32 "
        "{%0,%1,%2,%3}, {%4,%5,%6,%7}, {%8,%9}, {%0,%1,%2,%3};"
        : "+f"(c[0]), "+f"(c[1]), "+f"(c[2]), "+f"(c[3])
        : "r"(a0), "r"(a1), "r"(a2), "r"(a3), "r"(b0), "r"(b1));
}

// ---------------- GEMM1: h = relu(x @ W1 + b1), 3x-fp16 split (scaled lo) ----------------
// A[M,K] row-major, W1[K,N] row-major (col-major B for .row.col mma).
// hi = a & FFFFE000 (10 bits, fp16-exact); lo = (a-hi)*2048 in fp16.
// acc_hh += hiA*hiB ; acc_cr += hiA*loB + loA*hiB ; h = acc_hh + acc_cr/2048.
#define BM 128
#define BN 128
#define BK 32
#define ASTRIDE 40     // %32==8 -> conflict-free LDS.64 k-pairs
#define BSTRIDE 132    // %32==4 -> conflict-free LDS.32
#define ABYTES (BM * ASTRIDE * 4)     // 20480
#define BBYTES (BK * BSTRIDE * 4)     // 16896
#define STAGEBYTES (ABYTES + BBYTES)  // 37376
#define GSMEM (2 * STAGEBYTES)        // 74752
#define ZPT 96                        // fused zero chunks per CTA

#define SCALE_UP   2048.0f
#define SCALE_DOWN 4.8828125e-4f      // 1/2048

__global__ __launch_bounds__(256) void gemm1_tc(
    const float* __restrict__ A, const float* __restrict__ B,
    const float* __restrict__ bias, float* __restrict__ C,
    float4* __restrict__ zout)
{
    extern __shared__ float smem[];
    const int tid = threadIdx.x;
    const int warp = tid >> 5, lane = tid & 31;
    const int wm = (warp & 1) * 64;       // warp m-offset
    const int wn = (warp >> 1) * 32;      // warp n-offset
    const int row0 = blockIdx.y * BM;
    const int col0 = blockIdx.x * BN;
    const int r = lane >> 2, cq = lane & 3;
    const int ctalin = blockIdx.y * 32 + blockIdx.x;   // 0..1023

    const uint32_t sb = smem_u32(smem);

    if (ctalin == 0 && tid < NEXP) g_counts[tid] = 0;

    float acc_hh[4][4][4];   // [mtile][ntile][frag]
    float acc_cr[4][4][4];   // cross terms, scaled by 2048
    #pragma unroll
    for (int i = 0; i < 4; i++)
        #pragma unroll
        for (int j = 0; j < 4; j++)
            #pragma unroll
            for (int f = 0; f < 4; f++) { acc_hh[i][j][f] = 0.f; acc_cr[i][j][f] = 0.f; }

    auto fill = [&](int buf, int kc) {
        const uint32_t st = sb + buf * STAGEBYTES;
        #pragma unroll
        for (int t = 0; t < 4; t++) {          // A: 1024 x 16B chunks
            int o = tid + t * 256;
            int rr = o >> 3, c16 = o & 7;
            cpasync16(st + (rr * ASTRIDE + c16 * 4) * 4,
                      A + (size_t)(row0 + rr) * HDIM + kc + c16 * 4);
        }
        #pragma unroll
        for (int t = 0; t < 4; t++) {          // B: 1024 x 16B chunks
            int o = tid + t * 256;
            int rr = o >> 5, c16 = o & 31;
            cpasync16(st + ABYTES + (rr * BSTRIDE + c16 * 4) * 4,
                      B + (size_t)(kc + rr) * HDIM + col0 + c16 * 4);
        }
    };

    fill(0, 0);
    CP_COMMIT();

    const float4 z4 = make_float4(0.f, 0.f, 0.f, 0.f);
    const long long zbase = (long long)ctalin * (ZPT * 256) + tid;

    const int NCHUNK = HDIM / BK;   // 128
    for (int c = 0; c < NCHUNK; ++c) {
        if (c < ZPT) zout[zbase + (long long)c * 256] = z4;

        if (c + 1 < NCHUNK) { fill((c + 1) & 1, (c + 1) * BK); CP_COMMIT(); CP_WAIT(1); }
        else                { CP_WAIT(0); }
        __syncthreads();

        const float* As = smem + ((c & 1) * STAGEBYTES) / 4;
        const float* Bs = As + ABYTES / 4;

        #pragma unroll
        for (int kk = 0; kk < 2; kk++) {       // two k16 steps
            const int kof = kk * 16;

            // ---- A fragments (m16n8k16): R0=(r,2cq|+1) R1=(r+8,..) R2=(r,2cq+8|+9) R3=(r+8,..)
            uint32_t ahi[4][4], alo[4][4];
            #pragma unroll
            for (int mt = 0; mt < 4; mt++) {
                const float* pa = As + (size_t)(wm + mt * 16 + r) * ASTRIDE + kof + 2 * cq;
                float2 p0 = *(const float2*)(pa);
                float2 p1 = *(const float2*)(pa + 8 * ASTRIDE);
                float2 p2 = *(const float2*)(pa + 8);
                float2 p3 = *(const float2*)(pa + 8 * ASTRIDE + 8);
                float h;
                h = hi10(p0.x); float l0x = (p0.x - h) * SCALE_UP; float h0x = h;
                h = hi10(p0.y); float l0y = (p0.y - h) * SCALE_UP; float h0y = h;
                h = hi10(p1.x); float l1x = (p1.x - h) * SCALE_UP; float h1x = h;
                h = hi10(p1.y); float l1y = (p1.y - h) * SCALE_UP; float h1y = h;
                h = hi10(p2.x); float l2x = (p2.x - h) * SCALE_UP; float h2x = h;
                h = hi10(p2.y); float l2y = (p2.y - h) * SCALE_UP; float h2y = h;
                h = hi10(p3.x); float l3x = (p3.x - h) * SCALE_UP; float h3x = h;
                h = hi10(p3.y); float l3y = (p3.y - h) * SCALE_UP; float h3y = h;
                ahi[mt][0] = pk(h0x, h0y); alo[mt][0] = pk(l0x, l0y);
                ahi[mt][1] = pk(h1x, h1y); alo[mt][1] = pk(l1x, l1y);
                ahi[mt][2] = pk(h2x, h2y); alo[mt][2] = pk(l2x, l2y);
                ahi[mt][3] = pk(h3x, h3y); alo[mt][3] = pk(l3x, l3y);
            }
            // ---- B fragments: b0={B[2cq][n],B[2cq+1][n]} b1={B[2cq+8][n],B[2cq+9][n]}
            uint32_t bhi[4][2], blo[4][2];
            #pragma unroll
            for (int nt = 0; nt < 4; nt++) {
                const float* pb = Bs + (size_t)(kof + 2 * cq) * BSTRIDE + wn + nt * 8 + r;
                float q0 = pb[0];
                float q1 = pb[BSTRIDE];
                float q2 = pb[8 * BSTRIDE];
                float q3 = pb[9 * BSTRIDE];
                float h;
                h = hi10(q0); float m0 = (q0 - h) * SCALE_UP; float g0 = h;
                h = hi10(q1); float m1 = (q1 - h) * SCALE_UP; float g1 = h;
                h = hi10(q2); float m2 = (q2 - h) * SCALE_UP; float g2 = h;
                h = hi10(q3); float m3 = (q3 - h) * SCALE_UP; float g3 = h;
                bhi[nt][0] = pk(g0, g1); blo[nt][0] = pk(m0, m1);
                bhi[nt][1] = pk(g2, g3); blo[nt][1] = pk(m2, m3);
            }
            // ---- 3 passes (same-acc MMAs spaced; per-acc order hh then cross)
            #pragma unroll
            for (int mt = 0; mt < 4; mt++)
                #pragma unroll
                for (int nt = 0; nt < 4; nt++)
                    mma_f16(acc_hh[mt][nt], ahi[mt][0], ahi[mt][1], ahi[mt][2], ahi[mt][3],
                            bhi[nt][0], bhi[nt][1]);
            #pragma unroll
            for (int mt = 0; mt < 4; mt++)
                #pragma unroll
                for (int nt = 0; nt < 4; nt++)
                    mma_f16(acc_cr[mt][nt], ahi[mt][0], ahi[mt][1], ahi[mt][2], ahi[mt][3],
                            blo[nt][0], blo[nt][1]);
            #pragma unroll
            for (int mt = 0; mt < 4; mt++)
                #pragma unroll
                for (int nt = 0; nt < 4; nt++)
                    mma_f16(acc_cr[mt][nt], alo[mt][0], alo[mt][1], alo[mt][2], alo[mt][3],
                            bhi[nt][0], bhi[nt][1]);
        }
        __syncthreads();
    }

    // ---- epilogue: relu(hh + cr/2048 + bias) -> C ----
    // C frag: c0=(r, 2cq) c1=(r, 2cq+1) c2=(r+8, 2cq) c3=(r+8, 2cq+1)
    #pragma unroll
    for (int mt = 0; mt < 4; mt++) {
        #pragma unroll
        for (int nt = 0; nt < 4; nt++) {
            int col = col0 + wn + nt * 8 + 2 * cq;
            float bx = __ldg(bias + col), by = __ldg(bias + col + 1);
            int rowa = row0 + wm + mt * 16 + r;
            float2 v0, v1;
            v0.x = fmaxf(acc_hh[mt][nt][0] + acc_cr[mt][nt][0] * SCALE_DOWN + bx, 0.f);
            v0.y = fmaxf(acc_hh[mt][nt][1] + acc_cr[mt][nt][1] * SCALE_DOWN + by, 0.f);
            v1.x = fmaxf(acc_hh[mt][nt][2] + acc_cr[mt][nt][2] * SCALE_DOWN + bx, 0.f);
            v1.y = fmaxf(acc_hh[mt][nt][3] + acc_cr[mt][nt][3] * SCALE_DOWN + by, 0.f);
            *(float2*)(C + (size_t)rowa * HDIM + col) = v0;
            *(float2*)(C + (size_t)(rowa + 8) * HDIM + col) = v1;
        }
    }
}

// ---------------- GEMM2: logits = h @ W2 + b2 (one warp per token) ----------------
__global__ void gemm2_kernel(const float* __restrict__ h, const float* __restrict__ W2,
                             const float* __restrict__ b2, float* __restrict__ logits)
{
    int warp = (blockIdx.x * blockDim.x + threadIdx.x) >> 5;
    int lane = threadIdx.x & 31;
    if (warp >= NTOK) return;
    const float* hr = h + (size_t)warp * HDIM;

    float acc[NEXP];
    #pragma unroll
    for (int e = 0; e < NEXP; e++) acc[e] = 0.f;

    for (int k0 = lane * 4; k0 < HDIM; k0 += 128) {
        float4 hv = *(const float4*)(hr + k0);
        float hvv[4] = {hv.x, hv.y, hv.z, hv.w};
        #pragma unroll
        for (int j = 0; j < 4; j++) {
            const float* w = W2 + (size_t)(k0 + j) * NEXP;
            float4 w0 = *(const float4*)w;
            float4 w1 = *(const float4*)(w + 4);
            acc[0] += hvv[j] * w0.x; acc[1] += hvv[j] * w0.y;
            acc[2] += hvv[j] * w0.z; acc[3] += hvv[j] * w0.w;
            acc[4] += hvv[j] * w1.x; acc[5] += hvv[j] * w1.y;
            acc[6] += hvv[j] * w1.z; acc[7] += hvv[j] * w1.w;
        }
    }
    #pragma unroll
    for (int e = 0; e < NEXP; e++) {
        #pragma unroll
        for (int off = 16; off > 0; off >>= 1)
            acc[e] += __shfl_down_sync(0xffffffffu, acc[e], off);
    }
    if (lane == 0) {
        #pragma unroll
        for (int e = 0; e < NEXP; e++)
            logits[warp * NEXP + e] = acc[e] + b2[e];
    }
}

// ---------------- softmax + top-2 ----------------
__global__ void topk_kernel(const float* __restrict__ logits, float* __restrict__ probs_out)
{
    int t = blockIdx.x * blockDim.x + threadIdx.x;
    if (t >= NTOK) return;
    float l[NEXP];
    float m = -1e30f;
    #pragma unroll
    for (int e = 0; e < NEXP; e++) { l[e] = logits[t * NEXP + e]; m = fmaxf(m, l[e]); }
    float s = 0.f;
    #pragma unroll
    for (int e = 0; e < NEXP; e++) { l[e] = expf(l[e] - m); s += l[e]; }
    float inv = 1.f / s;
    float p[NEXP];
    #pragma unroll
    for (int e = 0; e < NEXP; e++) { p[e] = l[e] * inv; probs_out[t * NEXP + e] = p[e]; }

    int i1 = 0; float p1 = p[0];
    #pragma unroll
    for (int e = 1; e < NEXP; e++) if (p[e] > p1) { p1 = p[e]; i1 = e; }
    int i2 = -1; float p2 = -1.f;
    #pragma unroll
    for (int e = 0; e < NEXP; e++) if (e != i1 && p[e] > p2) { p2 = p[e]; i2 = e; }

    float norm = 1.f / (p1 + p2 + 1e-8f);
    g_flat_idx[2 * t + 0] = i1;
    g_flat_idx[2 * t + 1] = i2;
    g_flat_prob[2 * t + 0] = p1 * norm;
    g_flat_prob[2 * t + 1] = p2 * norm;
    atomicAdd(&g_counts[i1], 1);
    atomicAdd(&g_counts[i2], 1);
}

// ---------------- exclusive per-expert position scan ----------------
__device__ __forceinline__ uint4 add4(uint4 a, uint4 b) {
    return make_uint4(a.x + b.x, a.y + b.y, a.z + b.z, a.w + b.w);
}
__device__ __forceinline__ uint4 sub4(uint4 a, uint4 b) {
    return make_uint4(a.x - b.x, a.y - b.y, a.z - b.z, a.w - b.w);
}
__global__ __launch_bounds__(1024) void scan_kernel()
{
    const int tid = threadIdx.x;
    const int lane = tid & 31, wid = tid >> 5;

    int e[8];
    uint4 pre[8];
    uint4 run = make_uint4(0, 0, 0, 0);
    #pragma unroll
    for (int i = 0; i < 8; i++) {
        e[i] = g_flat_idx[tid * 8 + i];
        pre[i] = run;
        unsigned word = (unsigned)e[i] >> 1;
        unsigned add = 1u << ((e[i] & 1) * 16);
        if (word == 0) run.x += add;
        else if (word == 1) run.y += add;
        else if (word == 2) run.z += add;
        else run.w += add;
    }
    const uint4 own = run;

    uint4 incl = own;
    #pragma unroll
    for (int off = 1; off < 32; off <<= 1) {
        unsigned vx = __shfl_up_sync(0xffffffffu, incl.x, off);
        unsigned vy = __shfl_up_sync(0xffffffffu, incl.y, off);
        unsigned vz = __shfl_up_sync(0xffffffffu, incl.z, off);
        unsigned vw = __shfl_up_sync(0xffffffffu, incl.w, off);
        if (lane >= off) { incl.x += vx; incl.y += vy; incl.z += vz; incl.w += vw; }
    }

    __shared__ uint4 wtot[32];
    if (lane == 31) wtot[wid] = incl;
    __syncthreads();
    if (wid == 0) {
        uint4 v = wtot[lane];
        uint4 inc2 = v;
        #pragma unroll
        for (int off = 1; off < 32; off <<= 1) {
            unsigned vx = __shfl_up_sync(0xffffffffu, inc2.x, off);
            unsigned vy = __shfl_up_sync(0xffffffffu, inc2.y, off);
            unsigned vz = __shfl_up_sync(0xffffffffu, inc2.z, off);
            unsigned vw = __shfl_up_sync(0xffffffffu, inc2.w, off);
            if (lane >= off) { inc2.x += vx; inc2.y += vy; inc2.z += vz; inc2.w += vw; }
        }
        wtot[lane] = sub4(inc2, v);
    }
    __syncthreads();

    const uint4 base = add4(wtot[wid], sub4(incl, own));
    #pragma unroll
    for (int i = 0; i < 8; i++) {
        uint4 tot = add4(base, pre[i]);
        unsigned word = (unsigned)e[i] >> 1;
        unsigned w = (word == 0) ? tot.x : (word == 1) ? tot.y : (word == 2) ? tot.z : tot.w;
        g_pos[tid * 8 + i] = (int)((w >> ((e[i] & 1) * 16)) & 0xFFFFu);
    }
}

// ---------------- scatter ----------------
__global__ void scatter_kernel(float* __restrict__ dispatch, float* __restrict__ combine)
{
    int n = blockIdx.x * blockDim.x + threadIdx.x;
    if (n >= NSEL) return;
    int p = g_pos[n];
    if (p < CAP) {
        int tok = n >> 1;
        int e = g_flat_idx[n];
        size_t off = ((size_t)tok * NEXP + e) * CAP + p;
        dispatch[off] = 1.0f;
        combine[off] = g_flat_prob[n];
    }
}

// ---------------- aux loss ----------------
__global__ void aux_kernel(const float* __restrict__ probs, float* __restrict__ aux_out)
{
    __shared__ float sh[256];
    const int tid = threadIdx.x;
    float local[NEXP];
    #pragma unroll
    for (int e = 0; e < NEXP; e++) local[e] = 0.f;
    for (int t = tid; t < NTOK; t += 256) {
        #pragma unroll
        for (int e = 0; e < NEXP; e++) local[e] += probs[t * NEXP + e];
    }
    float aux = 0.f;
    for (int e = 0; e < NEXP; e++) {
        sh[tid] = local[e];
        __syncthreads();
        for (int s = 128; s > 0; s >>= 1) {
            if (tid < s) sh[tid] += sh[tid + s];
            __syncthreads();
        }
        if (tid == 0)
            aux += (sh[0] / (float)NTOK) * ((float)g_counts[e] / (float)NSEL) * (float)NEXP;
        __syncthreads();
    }
    if (tid == 0) *aux_out = aux;
}

// ---------------- launch ----------------
extern "C" void kernel_launch(void* const* d_in, const int* in_sizes, int n_in,
                              void* d_out, int out_size)
{
    const float* x  = (const float*)d_in[0];
    const float* W1 = (const float*)d_in[1];
    const float* b1 = (const float*)d_in[2];
    const float* W2 = (const float*)d_in[3];
    const float* b2 = (const float*)d_in[4];

    float* out      = (float*)d_out;
    float* dispatch = out;
    float* combine  = out + DISPATCH_ELEMS;
    float* probs    = out + PROBS_OFF;
    float* aux      = out + AUX_OFF;

    float* d_h;      cudaGetSymbolAddress((void**)&d_h, g_h);
    float* d_logits; cudaGetSymbolAddress((void**)&d_logits, g_logits);

    static bool attr_set = false;
    if (!attr_set) {
        cudaFuncSetAttribute(gemm1_tc, cudaFuncAttributeMaxDynamicSharedMemorySize, GSMEM);
        attr_set = true;
    }

    // 1) GEMM1 (3x-fp16 split mma.sync m16n8k16) + fused output zeroing
    gemm1_tc<<<dim3(HDIM / BN, NTOK / BM), 256, GSMEM>>>(x, W1, b1, d_h, (float4*)out);

    // 2) GEMM2
    gemm2_kernel<<<NTOK / 8, 256>>>(d_h, W2, b2, d_logits);

    // 3) softmax + top-2
    topk_kernel<<<NTOK / 256, 256>>>(d_logits, probs);

    // 4) capacity position scan
    scan_kernel<<<1, 1024>>>();

    // 5) scatter
    scatter_kernel<<<NSEL / 256, 256>>>(dispatch, combine);

    // 6) aux loss
    aux_kernel<<<1, 256>>>(probs, aux);
}